// round 1
// baseline (speedup 1.0000x reference)
#include <cuda_runtime.h>

// MPS chain contraction, fp32, D=3, 221 steps, 32768 independent chains.
// Each thread evolves TWO chains packed into f32x2 registers (Blackwell packed
// fp32 math). Samples are staged through shared memory (coalesced), pre-packed
// as float2 {elem e, elem e+64}. T is staged once per block, duplicated as
// (T,T) float2 so packed operands load directly via LDS.128.

#define NSTEPS 221
#define ROWF   693        // floats per chain row in global (231*3; only 221*3 used)
#define TC     17         // steps per staged chunk
#define NCH    13         // 13*17 = 221
#define CF     (TC*3)     // 51 floats per elem per chunk
#define NPAIR  64         // pairs per block (= blockDim.x)
#define EPB    (2*NPAIR)  // 128 elems per block
#define TROW   28         // padded float2 per T step row (27 used + 1 pad, 224B = 16B aligned)

typedef unsigned long long ull;

__device__ __forceinline__ ull pk2(float a, float b) {
    ull r; asm("mov.b64 %0, {%1, %2};" : "=l"(r) : "f"(a), "f"(b)); return r;
}
__device__ __forceinline__ float2 upk(ull v) {
    float2 r; asm("mov.b64 {%0, %1}, %2;" : "=f"(r.x), "=f"(r.y) : "l"(v)); return r;
}
__device__ __forceinline__ ull f2fma(ull a, ull b, ull c) {
    ull d; asm("fma.rn.f32x2 %0, %1, %2, %3;" : "=l"(d) : "l"(a), "l"(b), "l"(c)); return d;
}
__device__ __forceinline__ ull f2mul(ull a, ull b) {
    ull d; asm("mul.rn.f32x2 %0, %1, %2;" : "=l"(d) : "l"(a), "l"(b)); return d;
}

__global__ void __launch_bounds__(NPAIR)
mps_kernel(const float* __restrict__ S,
           const float* __restrict__ T,
           const float* __restrict__ B,
           float* __restrict__ out)
{
    extern __shared__ float2 sh[];
    float2* sT  = sh;                    // [221][28] duplicated (T,T) pairs
    float2* sX  = sh + NSTEPS * TROW;    // [64 pairs][51] sample pairs for one chunk
    float*  sXf = (float*)sX;

    const int tid  = threadIdx.x;
    const int base = blockIdx.x * EPB;

    // ---- stage duplicated T (once per block) ----
    for (int i = tid; i < NSTEPS * 27; i += NPAIR) {
        int t = i / 27, k = i - t * 27;
        float v = T[i];
        sT[t * TROW + k] = make_float2(v, v);
    }
    for (int i = tid; i < NSTEPS; i += NPAIR)
        sT[i * TROW + 27] = make_float2(0.f, 0.f);

    // ---- bias as duplicated pairs in registers (general: not assuming identity) ----
    ull Bp[9];
    #pragma unroll
    for (int i = 0; i < 9; i++) { float b = B[i]; Bp[i] = pk2(b, b); }

    // ---- state: v = e0 for both packed chains ----
    ull V0 = pk2(1.f, 1.f), V1 = pk2(0.f, 0.f), V2 = pk2(0.f, 0.f);

    const float* g0 = S + (size_t)base * ROWF;

    #pragma unroll 1
    for (int c = 0; c < NCH; c++) {
        // ---- cooperative staging of chunk c: 128 elems x 51 floats ----
        #pragma unroll 1
        for (int i = tid; i < EPB * CF; i += NPAIR) {
            int e = i / CF, j = i - e * CF;
            float v = g0[(size_t)e * ROWF + c * CF + j];
            // pair p = e&63, half h = e>>6 ; row stride 2*CF floats
            sXf[(e & (NPAIR - 1)) * (2 * CF) + j * 2 + (e >> 6)] = v;
        }
        __syncthreads();

        // ---- evolve 17 steps from smem ----
        #pragma unroll 1
        for (int tl = 0; tl < TC; tl++) {
            const int t = c * TC + tl;

            // load 27 duplicated T pairs via 14x LDS.128
            const float4* tq = (const float4*)(sT + t * TROW);
            ull Tp[27];
            #pragma unroll
            for (int k = 0; k < 14; k++) {
                float4 q = tq[k];
                if (2 * k     < 27) Tp[2 * k]     = pk2(q.x, q.y);
                if (2 * k + 1 < 27) Tp[2 * k + 1] = pk2(q.z, q.w);
            }

            // x pairs for this step (3x LDS.64)
            const float2* xp = sX + tid * CF + tl * 3;
            float2 a0 = xp[0], a1 = xp[1], a2 = xp[2];
            ull X0 = pk2(a0.x, a0.y);
            ull X1 = pk2(a1.x, a1.y);
            ull X2 = pk2(a2.x, a2.y);

            // m[l][r] = B[l][r] + sum_d x[d] * T[l][r][d]   (27 FMA2)
            ull m[9];
            #pragma unroll
            for (int l = 0; l < 3; l++) {
                #pragma unroll
                for (int r = 0; r < 3; r++) {
                    ull acc = f2fma(X0, Tp[l * 9 + r * 3 + 0], Bp[l * 3 + r]);
                    acc     = f2fma(X1, Tp[l * 9 + r * 3 + 1], acc);
                    acc     = f2fma(X2, Tp[l * 9 + r * 3 + 2], acc);
                    m[l * 3 + r] = acc;
                }
            }
            // v' = v * m   (9 FMA2)
            ull n0 = f2fma(V2, m[6], f2fma(V1, m[3], f2mul(V0, m[0])));
            ull n1 = f2fma(V2, m[7], f2fma(V1, m[4], f2mul(V0, m[1])));
            ull n2 = f2fma(V2, m[8], f2fma(V1, m[5], f2mul(V0, m[2])));
            V0 = n0; V1 = n1; V2 = n2;
        }
        __syncthreads();
    }

    // ---- write results: chains (base+tid) and (base+tid+64) ----
    float2 r0 = upk(V0), r1 = upk(V1), r2 = upk(V2);
    const int e0 = base + tid, e1 = e0 + NPAIR;
    out[e0 * 3 + 0] = r0.x; out[e0 * 3 + 1] = r1.x; out[e0 * 3 + 2] = r2.x;
    out[e1 * 3 + 0] = r0.y; out[e1 * 3 + 1] = r1.y; out[e1 * 3 + 2] = r2.y;
}

extern "C" void kernel_launch(void* const* d_in, const int* in_sizes, int n_in,
                              void* d_out, int out_size)
{
    const float* S = (const float*)d_in[0];   // samples  [32768, 693]
    const float* T = (const float*)d_in[1];   // tensors1 [221, 27]
    const float* B = (const float*)d_in[2];   // bias_mat [9]
    float* out = (float*)d_out;               // [32768, 3]

    const size_t smem = (size_t)(NSTEPS * TROW + NPAIR * CF) * sizeof(float2); // 75,616 B
    cudaFuncSetAttribute(mps_kernel, cudaFuncAttributeMaxDynamicSharedMemorySize, (int)smem);

    const int grid = 32768 / EPB;  // 256 blocks
    mps_kernel<<<grid, NPAIR, smem>>>(S, T, B, out);
}

// round 2
// speedup vs baseline: 3.9046x; 3.9046x over previous
#include <cuda_runtime.h>

// MPS chain contraction, fp32, D=3, 221 steps, 32768 chains.
// Round-2 strategy: exploit associativity. Kernel1: each thread computes the
// 3x3 matrix product of one 32-step SEGMENT for one PAIR of chains (f32x2
// packed math). 7 segments * 16384 pairs = 114688 threads (vs 16384 before).
// Kernel2: combines the 7 segment matrices per chain via scratch in a
// __device__ global array.

#define ROWF   693          // floats per chain row in global
#define NSTEPS 221
#define NSEG   7
#define SEGLEN 32           // last segment has 29
#define CSTEPS 8            // steps staged per chunk
#define NCHUNK 4
#define NP     32           // pairs per block
#define EPB    (2*NP)       // 64 elements per block
#define THR1   (NP*NSEG)    // 224 threads
#define NPAIRS 16384

typedef unsigned long long ull;

__device__ ull g_scratch[(size_t)NSEG * NPAIRS * 9];   // 8.26 MB segment matrices

__device__ __forceinline__ ull pk2(float a, float b) {
    ull r; asm("mov.b64 %0, {%1, %2};" : "=l"(r) : "f"(a), "f"(b)); return r;
}
__device__ __forceinline__ float2 upk(ull v) {
    float2 r; asm("mov.b64 {%0, %1}, %2;" : "=f"(r.x), "=f"(r.y) : "l"(v)); return r;
}
__device__ __forceinline__ ull f2fma(ull a, ull b, ull c) {
    ull d; asm("fma.rn.f32x2 %0, %1, %2, %3;" : "=l"(d) : "l"(a), "l"(b), "l"(c)); return d;
}
__device__ __forceinline__ ull f2mul(ull a, ull b) {
    ull d; asm("mul.rn.f32x2 %0, %1, %2;" : "=l"(d) : "l"(a), "l"(b)); return d;
}

// smem layout (ull units):
//   sT: [NSEG*CSTEPS][30]  duplicated (t,t) pairs, COLUMN-major per step:
//       idx30 = r*10 + l*3 + d   (pad entry 9 per column)
//   sX: [168][NP]          sample pairs; c = w*24 + i*3 + d
#define STN  (NSEG*CSTEPS*30)   // 1680
#define SXN  (168*NP)           // 5376
#define SMEM_ULL (STN + SXN)    // 7056 -> 56448 B

__global__ void __launch_bounds__(THR1)
mps_seg_kernel(const float* __restrict__ S,
               const float* __restrict__ T,
               const float* __restrict__ B)
{
    extern __shared__ ull sh[];
    ull* sT = sh;
    ull* sX = sh + STN;

    const int tid = threadIdx.x;
    const int p   = tid & 31;       // pair within block (= lane)
    const int s   = tid >> 5;       // segment (= warp id), 0..6
    const float* g0 = S + (size_t)blockIdx.x * EPB * ROWF;

    // bias, duplicated into packed regs
    ull Bp[9];
    #pragma unroll
    for (int i = 0; i < 9; i++) { float b = B[i]; Bp[i] = pk2(b, b); }

    // A = I (packed)
    ull A[9];
    #pragma unroll
    for (int i = 0; i < 9; i++) A[i] = pk2(0.f, 0.f);
    A[0] = A[4] = A[8] = pk2(1.f, 1.f);

    const int seglen = (s == NSEG - 1) ? (NSTEPS - SEGLEN * (NSEG - 1)) : SEGLEN; // 29 or 32

    #pragma unroll 1
    for (int k = 0; k < NCHUNK; k++) {
        // ---- stage T for this chunk: all 7 windows, 8 steps, 27 entries ----
        #pragma unroll 1
        for (int i = tid; i < NSEG * CSTEPS * 27; i += THR1) {
            int st  = i / 27;               // w*8 + ii
            int rem = i - st * 27;          // l*9 + r*3 + d
            int l = rem / 9, r2 = (rem - l * 9) / 3, d = rem - l * 9 - r2 * 3;
            int w = st >> 3, ii = st & 7;
            int t = w * SEGLEN + k * CSTEPS + ii;
            float v = (t < NSTEPS) ? T[t * 27 + rem] : 0.f;
            sT[st * 30 + r2 * 10 + l * 3 + d] = pk2(v, v);
        }
        // ---- stage X pairs: 64 elems x 7 windows x 24 floats ----
        #pragma unroll 1
        for (int i = tid; i < EPB * 168; i += THR1) {
            int e = i / 168, c = i - e * 168;
            int w = c / 24, j = c - w * 24;
            float v = g0[(size_t)e * ROWF + w * (SEGLEN * 3) + k * (CSTEPS * 3) + j];
            ((float*)sX)[(c * NP + (e & 31)) * 2 + (e >> 5)] = v;
        }
        __syncthreads();

        const int ns = min(CSTEPS, seglen - k * CSTEPS);   // warp-uniform
        #pragma unroll 1
        for (int ii = 0; ii < ns; ii++) {
            const ull* xb = sX + (s * 24 + ii * 3) * NP + p;
            ull X0 = xb[0];
            ull X1 = xb[NP];
            ull X2 = xb[2 * NP];
            const ull* tb = sT + (s * CSTEPS + ii) * 30;   // uniform per warp -> broadcast
            ull nA[9];
            #pragma unroll
            for (int r = 0; r < 3; r++) {
                const ulonglong2* q = (const ulonglong2*)(tb + r * 10);
                ulonglong2 q0 = q[0], q1 = q[1], q2 = q[2], q3 = q[3];
                ull t8 = tb[r * 10 + 8];
                // m column r: m_l = B[l][r] + sum_d x_d * T[l][r][d]
                ull m0 = f2fma(X2, q1.x, f2fma(X1, q0.y, f2fma(X0, q0.x, Bp[r])));
                ull m1 = f2fma(X2, q2.y, f2fma(X1, q2.x, f2fma(X0, q1.y, Bp[3 + r])));
                ull m2 = f2fma(X2, t8,   f2fma(X1, q3.y, f2fma(X0, q3.x, Bp[6 + r])));
                // newA[:,r] = A * m[:,r]
                nA[r]     = f2fma(A[2], m2, f2fma(A[1], m1, f2mul(A[0], m0)));
                nA[3 + r] = f2fma(A[5], m2, f2fma(A[4], m1, f2mul(A[3], m0)));
                nA[6 + r] = f2fma(A[8], m2, f2fma(A[7], m1, f2mul(A[6], m0)));
            }
            #pragma unroll
            for (int i = 0; i < 9; i++) A[i] = nA[i];
        }
        __syncthreads();
    }

    // write segment matrix
    const size_t P = (size_t)blockIdx.x * NP + p;
    ull* dst = g_scratch + ((size_t)s * NPAIRS + P) * 9;
    #pragma unroll
    for (int i = 0; i < 9; i++) dst[i] = A[i];
}

__global__ void __launch_bounds__(256)
mps_combine_kernel(float* __restrict__ out)
{
    const int P = blockIdx.x * 256 + threadIdx.x;   // pair id
    const ull* m0 = g_scratch + (size_t)P * 9;
    ull v0 = m0[0], v1 = m0[1], v2 = m0[2];         // row 0 of segment 0
    #pragma unroll
    for (int s = 1; s < NSEG; s++) {
        const ull* M = g_scratch + ((size_t)s * NPAIRS + P) * 9;
        ull a0 = M[0], a1 = M[1], a2 = M[2];
        ull a3 = M[3], a4 = M[4], a5 = M[5];
        ull a6 = M[6], a7 = M[7], a8 = M[8];
        ull n0 = f2fma(v2, a6, f2fma(v1, a3, f2mul(v0, a0)));
        ull n1 = f2fma(v2, a7, f2fma(v1, a4, f2mul(v0, a1)));
        ull n2 = f2fma(v2, a8, f2fma(v1, a5, f2mul(v0, a2)));
        v0 = n0; v1 = n1; v2 = n2;
    }
    float2 r0 = upk(v0), r1 = upk(v1), r2 = upk(v2);
    const int b = P >> 5, pp = P & 31;
    const int e0 = b * EPB + pp, e1 = e0 + NP;
    out[e0 * 3 + 0] = r0.x; out[e0 * 3 + 1] = r1.x; out[e0 * 3 + 2] = r2.x;
    out[e1 * 3 + 0] = r0.y; out[e1 * 3 + 1] = r1.y; out[e1 * 3 + 2] = r2.y;
}

extern "C" void kernel_launch(void* const* d_in, const int* in_sizes, int n_in,
                              void* d_out, int out_size)
{
    const float* S = (const float*)d_in[0];   // samples  [32768, 693]
    const float* T = (const float*)d_in[1];   // tensors1 [221, 27]
    const float* B = (const float*)d_in[2];   // bias_mat [9]
    float* out = (float*)d_out;               // [32768, 3]

    const size_t smem = (size_t)SMEM_ULL * sizeof(ull);   // 56448 B
    static int configured = 0;
    cudaFuncSetAttribute(mps_seg_kernel, cudaFuncAttributeMaxDynamicSharedMemorySize, (int)smem);
    (void)configured;

    mps_seg_kernel<<<32768 / EPB, THR1, smem>>>(S, T, B);   // 512 blocks
    mps_combine_kernel<<<NPAIRS / 256, 256>>>(out);         // 64 blocks
}